// round 10
// baseline (speedup 1.0000x reference)
#include <cuda_runtime.h>
#include <cstdint>

// Embedder, single fused kernel. out(x) = w2@relu(w1*x+b1)+b2 is piecewise
// linear in x with <=16 kinks: out[d](x) = A[seg][d]*x + B[seg][d], 17 segs.
// Each block rebuilds the 8.7KB A/B table in SHARED (trivial cost), so there
// is no prepass launch at all. Token positions gather emb_table rows (L2);
// numeric positions are 2 LDS.128 + FMA. Thresholds live in registers.

#define EMBED_DIM 64
#define NSEG 17

__global__ __launch_bounds__(256) void embedder_fused_kernel(
    const float* __restrict__ input_ids,
    const int*   __restrict__ type_mask,
    const float* __restrict__ emb_table,
    const float* __restrict__ w1,
    const float* __restrict__ b1,
    const float* __restrict__ w2,
    const float* __restrict__ b2,
    float*       __restrict__ out,
    int n_pos)
{
    __shared__ float s_A[NSEG][EMBED_DIM];   // 4352 B
    __shared__ float s_B[NSEG][EMBED_DIM];   // 4352 B
    __shared__ float s_t[16];

    // ---- per-block segment-table build (~1088 entries / 256 threads) ----
    {
        float w1v[16], b1v[16], t[16];
        bool  sgn[16];
#pragma unroll
        for (int j = 0; j < 16; ++j) {
            w1v[j] = __ldg(&w1[j]);
            b1v[j] = __ldg(&b1[j]);
            if (w1v[j] != 0.0f) { t[j] = -b1v[j] / w1v[j]; sgn[j] = (w1v[j] > 0.0f); }
            else { sgn[j] = true; t[j] = (b1v[j] > 0.0f) ? -1e30f : 1e30f; }
        }
        int rank[16];
#pragma unroll
        for (int j = 0; j < 16; ++j) {
            int r = 0;
#pragma unroll
            for (int k = 0; k < 16; ++k)
                r += (t[k] < t[j]) || (t[k] == t[j] && k < j);
            rank[j] = r;
        }
        if (threadIdx.x < 16) s_t[threadIdx.x] = t[threadIdx.x];

        for (int idx = threadIdx.x; idx < NSEG * EMBED_DIM; idx += blockDim.x) {
            const int seg = idx >> 6;       // 0..16
            const int d   = idx & 63;       // 0..63
            float A = 0.0f, B = __ldg(&b2[d]);
#pragma unroll
            for (int j = 0; j < 16; ++j) {
                const bool gt = (seg > rank[j]);          // x > t_j on this seg
                if (sgn[j] ? gt : !gt) {                  // relu active
                    const float w = __ldg(&w2[d * 16 + j]);
                    A = fmaf(w, w1v[j], A);
                    B = fmaf(w, b1v[j], B);
                }
            }
            s_A[seg][d] = A;
            s_B[seg][d] = B;
        }
    }
    __syncthreads();

    // thresholds into registers: seg compute becomes pure ALU
    float tr[16];
#pragma unroll
    for (int j = 0; j < 16; ++j) tr[j] = s_t[j];

    // ---- gather / piecewise-linear eval: one 32-pos chunk per warp ----
    const int lane = threadIdx.x & 31;
    const int half = lane >> 4;
    const int sub  = lane & 15;
    const int c    = (int)((blockIdx.x * blockDim.x + threadIdx.x) >> 5);
    const int base = c << 5;
    if (base >= n_pos) return;
    const int pos_l = base + lane;

    // pk layout: [15:0]=id, [16]=mask, [21:17]=seg
    int pk = 0;
    if (pos_l < n_pos) {
        const int id = (int)__ldg(&input_ids[pos_l]);
        const int m  = __ldg(&type_mask[pos_l]);
        const float x = (float)id;
        int seg = 0;
#pragma unroll
        for (int j = 0; j < 16; ++j) seg += (x > tr[j]);
        pk = id | (m << 16) | (seg << 17);
    }
    const int pmax = (n_pos - base < 32) ? (n_pos - base) : 32;

    const float4* sA4 = reinterpret_cast<const float4*>(&s_A[0][0]);
    const float4* sB4 = reinterpret_cast<const float4*>(&s_B[0][0]);
    float4* out4 = reinterpret_cast<float4*>(out);

#pragma unroll
    for (int p = 0; p < 32; p += 16) {           // 8 pairs per group
        int pks[8]; float4 r[8];
#pragma unroll
        for (int q = 0; q < 8; ++q)
            pks[q] = __shfl_sync(0xffffffffu, pk, p + 2 * q + half);
        // token gathers first: up to 8 independent 256B rows in flight
#pragma unroll
        for (int q = 0; q < 8; ++q) {
            if (pks[q] & 0x10000) {
                const int id = pks[q] & 0xFFFF;
                r[q] = __ldg(reinterpret_cast<const float4*>(
                           emb_table + (size_t)id * 64) + sub);
            }
        }
        // numeric: 2x LDS.128 + fma, overlaps in-flight gathers
#pragma unroll
        for (int q = 0; q < 8; ++q) {
            if (!(pks[q] & 0x10000)) {
                const int sg = pks[q] >> 17;
                const float x = (float)(pks[q] & 0xFFFF);
                const float4 A = sA4[sg * 16 + sub];
                const float4 B = sB4[sg * 16 + sub];
                r[q].x = fmaf(A.x, x, B.x);
                r[q].y = fmaf(A.y, x, B.y);
                r[q].z = fmaf(A.z, x, B.z);
                r[q].w = fmaf(A.w, x, B.w);
            }
        }
        if (p + 16 <= pmax) {
#pragma unroll
            for (int q = 0; q < 8; ++q)
                __stcs(&out4[(size_t)(base + p + 2 * q + half) * 16 + sub], r[q]);
        } else {
#pragma unroll
            for (int q = 0; q < 8; ++q) {
                const int pp = p + 2 * q + half;
                if (pp < pmax)
                    __stcs(&out4[(size_t)(base + pp) * 16 + sub], r[q]);
            }
        }
    }
}

extern "C" void kernel_launch(void* const* d_in, const int* in_sizes, int n_in,
                              void* d_out, int out_size)
{
    const float* input_ids = (const float*)d_in[0];
    const int*   type_mask = (const int*)  d_in[1];
    const float* emb_table = (const float*)d_in[2];
    const float* w1        = (const float*)d_in[3];
    const float* b1        = (const float*)d_in[4];
    const float* w2        = (const float*)d_in[5];
    const float* b2        = (const float*)d_in[6];
    float*       out       = (float*)d_out;

    const int n_pos = in_sizes[0];  // B*S = 524288

    const int nchunk = (n_pos + 31) >> 5;
    const int blocks = (nchunk + 7) >> 3;     // 8 warps per block, 1 chunk/warp
    embedder_fused_kernel<<<blocks, 256>>>(input_ids, type_mask, emb_table,
                                           w1, b1, w2, b2, out, n_pos);
}

// round 11
// speedup vs baseline: 1.8857x; 1.8857x over previous
#include <cuda_runtime.h>
#include <cstdint>

// Embedder, single fused kernel. out(x) = w2@relu(w1*x+b1)+b2 is piecewise
// linear in x with <=16 kinks: out[d](x) = A[seg][d]*x + B[seg][d], 17 segs.
// Each block rebuilds the 8.7KB A/B table in shared — but now the build is
// cheap: all weights staged into shared COALESCED first, thresholds/ranks
// computed once by 16 threads, and the grid is persistent (592 blocks) so
// the build is paid ~4x/SM, not 14x.

#define EMBED_DIM 64
#define NSEG 17

__global__ __launch_bounds__(256) void embedder_fused_kernel(
    const float* __restrict__ input_ids,
    const int*   __restrict__ type_mask,
    const float* __restrict__ emb_table,
    const float* __restrict__ w1,
    const float* __restrict__ b1,
    const float* __restrict__ w2,
    const float* __restrict__ b2,
    float*       __restrict__ out,
    int n_pos)
{
    __shared__ float s_A[NSEG][EMBED_DIM];     // 4352 B
    __shared__ float s_B[NSEG][EMBED_DIM];     // 4352 B
    __shared__ float s_w2t[16][EMBED_DIM + 1]; // transposed w2, padded
    __shared__ float s_w1[16], s_b1[16], s_b2[EMBED_DIM];
    __shared__ float s_t[16];
    __shared__ int   s_rank[16];

    // ---- stage weights coalesced ----
    for (int idx = threadIdx.x; idx < 1024; idx += blockDim.x) {
        const float v = w2[idx];                  // coalesced
        s_w2t[idx & 15][idx >> 4] = v;            // padded: no write conflicts
    }
    if (threadIdx.x < 16) {
        s_w1[threadIdx.x] = w1[threadIdx.x];
        s_b1[threadIdx.x] = b1[threadIdx.x];
    }
    if (threadIdx.x < EMBED_DIM) s_b2[threadIdx.x] = b2[threadIdx.x];
    __syncthreads();

    // ---- thresholds + ranks: 16 threads, once ----
    if (threadIdx.x < 16) {
        const int j = threadIdx.x;
        const float w = s_w1[j], b = s_b1[j];
        float t;
        if (w != 0.0f) t = -b / w;
        else           t = (b > 0.0f) ? -1e30f : 1e30f;
        s_t[j] = t;
    }
    __syncthreads();
    if (threadIdx.x < 16) {
        const int j = threadIdx.x;
        const float tj = s_t[j];
        int r = 0;
#pragma unroll
        for (int k = 0; k < 16; ++k)
            r += (s_t[k] < tj) || (s_t[k] == tj && k < j);
        s_rank[j] = r;
    }
    __syncthreads();

    // ---- build A/B: 1088 entries / 256 threads, all operands in shared ----
    for (int idx = threadIdx.x; idx < NSEG * EMBED_DIM; idx += blockDim.x) {
        const int seg = idx >> 6;
        const int d   = idx & 63;
        float A = 0.0f, B = s_b2[d];
#pragma unroll
        for (int j = 0; j < 16; ++j) {
            const bool gt = (seg > s_rank[j]);
            const bool active = (s_w1[j] > 0.0f) ? gt
                              : (s_w1[j] < 0.0f) ? !gt
                              : gt;                // w1==0: t=+-1e30 handles it
            if (active) {
                const float w = s_w2t[j][d];       // conflict-free LDS
                A = fmaf(w, s_w1[j], A);
                B = fmaf(w, s_b1[j], B);
            }
        }
        s_A[seg][d] = A;
        s_B[seg][d] = B;
    }
    __syncthreads();

    // thresholds into registers: seg compute is pure ALU
    float tr[16];
#pragma unroll
    for (int j = 0; j < 16; ++j) tr[j] = s_t[j];

    // ---- persistent gather: grid-stride over 32-pos chunks ----
    const int lane  = threadIdx.x & 31;
    const int half  = lane >> 4;
    const int sub   = lane & 15;
    const int warp  = (int)((blockIdx.x * blockDim.x + threadIdx.x) >> 5);
    const int nwarp = (int)((gridDim.x * blockDim.x) >> 5);
    const int nchunk = (n_pos + 31) >> 5;

    const float4* sA4 = reinterpret_cast<const float4*>(&s_A[0][0]);
    const float4* sB4 = reinterpret_cast<const float4*>(&s_B[0][0]);
    float4* out4 = reinterpret_cast<float4*>(out);

    for (int c = warp; c < nchunk; c += nwarp) {
        const int base  = c << 5;
        const int pos_l = base + lane;

        // pk layout: [15:0]=id, [16]=mask, [21:17]=seg
        int pk = 0;
        if (pos_l < n_pos) {
            const int id = (int)__ldg(&input_ids[pos_l]);
            const int m  = __ldg(&type_mask[pos_l]);
            const float x = (float)id;
            int seg = 0;
#pragma unroll
            for (int j = 0; j < 16; ++j) seg += (x > tr[j]);
            pk = id | (m << 16) | (seg << 17);
        }
        const int pmax = (n_pos - base < 32) ? (n_pos - base) : 32;

#pragma unroll
        for (int p = 0; p < 32; p += 16) {           // 8 pairs per group
            int pks[8]; float4 r[8];
#pragma unroll
            for (int q = 0; q < 8; ++q)
                pks[q] = __shfl_sync(0xffffffffu, pk, p + 2 * q + half);
            // token gathers first: up to 8 independent 256B rows in flight
#pragma unroll
            for (int q = 0; q < 8; ++q) {
                if (pks[q] & 0x10000) {
                    const int id = pks[q] & 0xFFFF;
                    r[q] = __ldg(reinterpret_cast<const float4*>(
                               emb_table + (size_t)id * 64) + sub);
                }
            }
            // numeric: 2x LDS.128 + fma, overlaps in-flight gathers
#pragma unroll
            for (int q = 0; q < 8; ++q) {
                if (!(pks[q] & 0x10000)) {
                    const int sg = pks[q] >> 17;
                    const float x = (float)(pks[q] & 0xFFFF);
                    const float4 A = sA4[sg * 16 + sub];
                    const float4 B = sB4[sg * 16 + sub];
                    r[q].x = fmaf(A.x, x, B.x);
                    r[q].y = fmaf(A.y, x, B.y);
                    r[q].z = fmaf(A.z, x, B.z);
                    r[q].w = fmaf(A.w, x, B.w);
                }
            }
            if (p + 16 <= pmax) {
#pragma unroll
                for (int q = 0; q < 8; ++q)
                    __stcs(&out4[(size_t)(base + p + 2 * q + half) * 16 + sub], r[q]);
            } else {
#pragma unroll
                for (int q = 0; q < 8; ++q) {
                    const int pp = p + 2 * q + half;
                    if (pp < pmax)
                        __stcs(&out4[(size_t)(base + pp) * 16 + sub], r[q]);
                }
            }
        }
    }
}

extern "C" void kernel_launch(void* const* d_in, const int* in_sizes, int n_in,
                              void* d_out, int out_size)
{
    const float* input_ids = (const float*)d_in[0];
    const int*   type_mask = (const int*)  d_in[1];
    const float* emb_table = (const float*)d_in[2];
    const float* w1        = (const float*)d_in[3];
    const float* b1        = (const float*)d_in[4];
    const float* w2        = (const float*)d_in[5];
    const float* b2        = (const float*)d_in[6];
    float*       out       = (float*)d_out;

    const int n_pos = in_sizes[0];  // B*S = 524288

    // Persistent: 148 SMs x 4 resident CTAs; build paid once per CTA slot
    embedder_fused_kernel<<<592, 256>>>(input_ids, type_mask, emb_table,
                                        w1, b1, w2, b2, out, n_pos);
}

// round 12
// speedup vs baseline: 2.4254x; 1.2862x over previous
#include <cuda_runtime.h>
#include <cstdint>

// Embedder, single fused kernel. out(x) = w2@relu(w1*x+b1)+b2 is piecewise
// linear in x (<=16 kinks): out[d](x) = A[seg][d]*x + B[seg][d], 17 segs.
// Each persistent block builds the 8.7KB A/B table in shared (cheap: weights
// staged coalesced), then grid-strides over 32-position chunks. Register
// diet (launch_bounds(256,4), 4-deep pipeline, thresholds read from shared)
// keeps 4 CTAs/SM resident for the gather phase.

#define EMBED_DIM 64
#define NSEG 17

__global__ __launch_bounds__(256, 4) void embedder_fused_kernel(
    const float* __restrict__ input_ids,
    const int*   __restrict__ type_mask,
    const float* __restrict__ emb_table,
    const float* __restrict__ w1,
    const float* __restrict__ b1,
    const float* __restrict__ w2,
    const float* __restrict__ b2,
    float*       __restrict__ out,
    int n_pos)
{
    __shared__ float s_A[NSEG][EMBED_DIM];     // 4352 B
    __shared__ float s_B[NSEG][EMBED_DIM];     // 4352 B
    __shared__ float s_w2t[16][EMBED_DIM + 1]; // transposed w2, padded
    __shared__ float s_w1[16], s_b1[16], s_b2[EMBED_DIM];
    __shared__ float s_t[16];
    __shared__ int   s_rank[16];

    // ---- stage weights coalesced ----
    for (int idx = threadIdx.x; idx < 1024; idx += blockDim.x)
        s_w2t[idx & 15][idx >> 4] = w2[idx];
    if (threadIdx.x < 16) {
        s_w1[threadIdx.x] = w1[threadIdx.x];
        s_b1[threadIdx.x] = b1[threadIdx.x];
    }
    if (threadIdx.x < EMBED_DIM) s_b2[threadIdx.x] = b2[threadIdx.x];
    __syncthreads();

    // ---- thresholds + ranks: 16 threads, once ----
    if (threadIdx.x < 16) {
        const int j = threadIdx.x;
        const float w = s_w1[j], b = s_b1[j];
        s_t[j] = (w != 0.0f) ? (-b / w) : ((b > 0.0f) ? -1e30f : 1e30f);
    }
    __syncthreads();
    if (threadIdx.x < 16) {
        const int j = threadIdx.x;
        const float tj = s_t[j];
        int r = 0;
#pragma unroll
        for (int k = 0; k < 16; ++k)
            r += (s_t[k] < tj) || (s_t[k] == tj && k < j);
        s_rank[j] = r;
    }
    __syncthreads();

    // ---- build A/B: 1088 entries / 256 threads, operands in shared ----
    for (int idx = threadIdx.x; idx < NSEG * EMBED_DIM; idx += blockDim.x) {
        const int seg = idx >> 6;
        const int d   = idx & 63;
        float A = 0.0f, B = s_b2[d];
#pragma unroll
        for (int j = 0; j < 16; ++j) {
            const bool gt = (seg > s_rank[j]);
            const bool active = (s_w1[j] > 0.0f) ? gt
                              : (s_w1[j] < 0.0f) ? !gt
                              : gt;               // w1==0: t=+-1e30 handles it
            if (active) {
                const float w = s_w2t[j][d];
                A = fmaf(w, s_w1[j], A);
                B = fmaf(w, s_b1[j], B);
            }
        }
        s_A[seg][d] = A;
        s_B[seg][d] = B;
    }
    __syncthreads();

    // ---- persistent gather: grid-stride over 32-pos chunks ----
    const int lane  = threadIdx.x & 31;
    const int half  = lane >> 4;
    const int sub   = lane & 15;
    const int warp  = (int)((blockIdx.x * blockDim.x + threadIdx.x) >> 5);
    const int nwarp = (int)((gridDim.x * blockDim.x) >> 5);
    const int nchunk = (n_pos + 31) >> 5;

    const float4* sA4 = reinterpret_cast<const float4*>(&s_A[0][0]);
    const float4* sB4 = reinterpret_cast<const float4*>(&s_B[0][0]);
    float4* out4 = reinterpret_cast<float4*>(out);

    for (int c = warp; c < nchunk; c += nwarp) {
        const int base  = c << 5;
        const int pos_l = base + lane;

        // pk layout: [15:0]=id, [16]=mask, [21:17]=seg
        int pk = 0;
        if (pos_l < n_pos) {
            const int id = (int)__ldg(&input_ids[pos_l]);
            const int m  = __ldg(&type_mask[pos_l]);
            const float x = (float)id;
            int seg = 0;
#pragma unroll
            for (int j = 0; j < 16; ++j) seg += (x > s_t[j]);  // broadcast LDS
            pk = id | (m << 16) | (seg << 17);
        }
        const int pmax = (n_pos - base < 32) ? (n_pos - base) : 32;

#pragma unroll
        for (int p = 0; p < 32; p += 8) {            // 4 pairs per group
            int pks[4]; float4 r[4];
#pragma unroll
            for (int q = 0; q < 4; ++q)
                pks[q] = __shfl_sync(0xffffffffu, pk, p + 2 * q + half);
            // token gathers first: 4 independent 256B rows in flight
#pragma unroll
            for (int q = 0; q < 4; ++q) {
                if (pks[q] & 0x10000) {
                    const int id = pks[q] & 0xFFFF;
                    r[q] = __ldg(reinterpret_cast<const float4*>(
                               emb_table + (size_t)id * 64) + sub);
                }
            }
            // numeric: 2x LDS.128 + fma, overlaps in-flight gathers
#pragma unroll
            for (int q = 0; q < 4; ++q) {
                if (!(pks[q] & 0x10000)) {
                    const int sg = pks[q] >> 17;
                    const float x = (float)(pks[q] & 0xFFFF);
                    const float4 A = sA4[sg * 16 + sub];
                    const float4 B = sB4[sg * 16 + sub];
                    r[q].x = fmaf(A.x, x, B.x);
                    r[q].y = fmaf(A.y, x, B.y);
                    r[q].z = fmaf(A.z, x, B.z);
                    r[q].w = fmaf(A.w, x, B.w);
                }
            }
            if (p + 8 <= pmax) {
#pragma unroll
                for (int q = 0; q < 4; ++q)
                    __stcs(&out4[(size_t)(base + p + 2 * q + half) * 16 + sub], r[q]);
            } else {
#pragma unroll
                for (int q = 0; q < 4; ++q) {
                    const int pp = p + 2 * q + half;
                    if (pp < pmax)
                        __stcs(&out4[(size_t)(base + pp) * 16 + sub], r[q]);
                }
            }
        }
    }
}

extern "C" void kernel_launch(void* const* d_in, const int* in_sizes, int n_in,
                              void* d_out, int out_size)
{
    const float* input_ids = (const float*)d_in[0];
    const int*   type_mask = (const int*)  d_in[1];
    const float* emb_table = (const float*)d_in[2];
    const float* w1        = (const float*)d_in[3];
    const float* b1        = (const float*)d_in[4];
    const float* w2        = (const float*)d_in[5];
    const float* b2        = (const float*)d_in[6];
    float*       out       = (float*)d_out;

    const int n_pos = in_sizes[0];  // B*S = 524288

    // Persistent: 148 SMs x 4 resident CTAs; build paid 4x/SM
    embedder_fused_kernel<<<592, 256>>>(input_ids, type_mask, emb_table,
                                        w1, b1, w2, b2, out, n_pos);
}